// round 4
// baseline (speedup 1.0000x reference)
#include <cuda_runtime.h>
#include <math.h>

#define DD  256
#define TT  128
#define BB  2
#define BT  256
#define LL  8
#define HH  4
#define DHH 64
#define FF  2048
#define NC  2048

typedef unsigned long long ULL;

// ---------------- device scratch ----------------
__device__ float g_qcls[DD];
__device__ float g_vcls[DD];
__device__ float g_scls[HH];
__device__ float g_bias0[DD];      // cls_token + bo
__device__ float g_kf[BT*DD];
__device__ float g_vf[BT*DD];
__device__ float g_sf[BT*HH];
__device__ float g_o0[NC*DD];
__device__ float g_x0[NC*DD];
__device__ float g_h2[NC*DD];
__device__ float g_u [NC*FF];
__device__ float g_enc[NC*DD];
__device__ float g_part[8*NC*DD];
__device__ int   g_lstar[BT];
__device__ int   g_slot[BB*TT];
__device__ int   g_cnt[BB];

// ---------------- f32x2 helpers ----------------
__device__ __forceinline__ ULL dup2(float x){
    ULL r; unsigned u = __float_as_uint(x);
    asm("mov.b64 %0, {%1, %1};" : "=l"(r) : "r"(u));
    return r;
}
__device__ __forceinline__ void fma2(ULL &c, ULL a, ULL b){
    asm("fma.rn.f32x2 %0, %1, %2, %0;" : "+l"(c) : "l"(a), "l"(b));
}
__device__ __forceinline__ float2 unpack2(ULL p){
    unsigned lo, hi;
    asm("mov.b64 {%0, %1}, %2;" : "=r"(lo), "=r"(hi) : "l"(p));
    return make_float2(__uint_as_float(lo), __uint_as_float(hi));
}

__device__ __forceinline__ float blockReduceSum256(float v, float* red){
    int t = threadIdx.x;
    red[t] = v; __syncthreads();
    #pragma unroll
    for (int s = 128; s > 0; s >>= 1){
        if (t < s) red[t] += red[t + s];
        __syncthreads();
    }
    float r = red[0];
    __syncthreads();
    return r;
}

// ---------------- kernel C: CLS precompute (1 block) — R2 numerics ----------------
__global__ void kC(const float* __restrict__ cls,
                   const float* __restrict__ Wq, const float* __restrict__ bq,
                   const float* __restrict__ Wk, const float* __restrict__ bk,
                   const float* __restrict__ Wv, const float* __restrict__ bv,
                   const float* __restrict__ bo,
                   const float* __restrict__ g1, const float* __restrict__ b1){
    __shared__ float red[256];
    __shared__ float h[DD];
    int t = threadIdx.x;
    float x = cls[t];
    float mean = blockReduceSum256(x, red) * (1.f/DD);
    float dx = x - mean;
    float var = blockReduceSum256(dx*dx, red) * (1.f/DD);
    float hn = dx * rsqrtf(var + 1e-5f) * g1[t] + b1[t];
    h[t] = hn; __syncthreads();

    float q = bq[t], k = bk[t], v = bv[t];
    #pragma unroll 8
    for (int j = 0; j < DD; j++){
        float hj = h[j];
        q += hj * Wq[j*DD + t];
        k += hj * Wk[j*DD + t];
        v += hj * Wv[j*DD + t];
    }
    g_qcls[t] = q;
    g_vcls[t] = v;
    g_bias0[t] = cls[t] + bo[t];

    red[t] = q * k; __syncthreads();
    if (t < HH){
        float s = 0.f;
        #pragma unroll
        for (int d = 0; d < DHH; d++) s += red[t*DHH + d];
        g_scls[t] = s * 0.125f;
    }
}

// ---------------- kernel P: per-frame LN1 + K/V + score, 4 frames/block (R2) ------
__global__ void kP(const float* __restrict__ frames,
                   const float* __restrict__ Wk, const float* __restrict__ bk,
                   const float* __restrict__ Wv, const float* __restrict__ bv,
                   const float* __restrict__ g1, const float* __restrict__ b1){
    __shared__ float red[256];
    __shared__ float hs[4][DD];
    int blk = blockIdx.x;
    int t = threadIdx.x;
    #pragma unroll
    for (int f = 0; f < 4; f++){
        float x = frames[(blk*4 + f)*DD + t];
        float mean = blockReduceSum256(x, red) * (1.f/DD);
        float dx = x - mean;
        float var = blockReduceSum256(dx*dx, red) * (1.f/DD);
        hs[f][t] = dx * rsqrtf(var + 1e-5f) * g1[t] + b1[t];
    }
    __syncthreads();

    float kk[4], vv[4];
    #pragma unroll
    for (int f = 0; f < 4; f++){ kk[f] = bk[t]; vv[f] = bv[t]; }
    #pragma unroll 4
    for (int j = 0; j < DD; j++){
        float wk = Wk[j*DD + t], wv = Wv[j*DD + t];
        #pragma unroll
        for (int f = 0; f < 4; f++){
            kk[f] += hs[f][j] * wk;
            vv[f] += hs[f][j] * wv;
        }
    }
    #pragma unroll
    for (int f = 0; f < 4; f++){
        g_kf[(blk*4 + f)*DD + t] = kk[f];
        g_vf[(blk*4 + f)*DD + t] = vv[f];
    }
    float qc = g_qcls[t];
    #pragma unroll
    for (int f = 0; f < 4; f++){
        red[t] = qc * kk[f]; __syncthreads();
        if (t < HH){
            float s = 0.f;
            #pragma unroll
            for (int d = 0; d < DHH; d++) s += red[t*DHH + d];
            g_sf[(blk*4 + f)*HH + t] = s * 0.125f;
        }
        __syncthreads();
    }
}

// ---------------- kernel A: attention (CLS query) for all 8 lengths (R2) ----------
__global__ void kA(){
    __shared__ float vsh[9][DD];
    __shared__ float sh_s[HH][9];
    __shared__ float wsh[LL][HH][9];
    int blk = blockIdx.x;
    int b = blk >> 7;
    int i = blk & 127;
    int t = threadIdx.x;

    vsh[0][t] = g_vcls[t];
    #pragma unroll
    for (int tt = 0; tt < 8; tt++)
        vsh[tt+1][t] = (i + tt < TT) ? g_vf[(b*TT + i + tt)*DD + t] : 0.f;

    if (t < 36){
        int hh = t / 9, idx = t % 9;
        float s;
        if (idx == 0) s = g_scls[hh];
        else {
            int tt = idx - 1;
            s = (i + tt < TT) ? g_sf[(b*TT + i + tt)*HH + hh] : -1e30f;
        }
        sh_s[hh][idx] = s;
    }
    __syncthreads();

    if (t < 32){
        int l  = (t >> 2) + 1;
        int hh = t & 3;
        float m = sh_s[hh][0];
        for (int tt = 0; tt < l; tt++)
            if (i + tt < TT) m = fmaxf(m, sh_s[hh][tt+1]);
        float e0 = expf(sh_s[hh][0] - m);
        float sum = e0;
        float e[8];
        #pragma unroll
        for (int tt = 0; tt < 8; tt++){
            bool inc = (tt < l) && (i + tt < TT);
            e[tt] = inc ? expf(sh_s[hh][tt+1] - m) : 0.f;
            sum += e[tt];
        }
        float inv = 1.f / sum;
        wsh[l-1][hh][0] = e0 * inv;
        #pragma unroll
        for (int tt = 0; tt < 8; tt++) wsh[l-1][hh][tt+1] = e[tt] * inv;
    }
    __syncthreads();

    int hd = t >> 6;
    #pragma unroll
    for (int l = 0; l < LL; l++){
        float acc = wsh[l][hd][0] * vsh[0][t];
        #pragma unroll
        for (int tt = 0; tt < 8; tt++)
            acc += wsh[l][hd][tt+1] * vsh[tt+1][t];
        g_o0[(blk*LL + l)*DD + t] = acc;
    }
}

// ---------------- f32x2 SGEMM: 128x128 tile, dup-A smem, double buffered ----------
template<int EPI, bool SPLIT>
__global__ __launch_bounds__(256, 2)
void sgemm128(const float* __restrict__ A, const float* __restrict__ B,
              const float* __restrict__ bias, const float* __restrict__ res,
              float* __restrict__ C, int M, int N, int Kblk, int Ktot){
    __shared__ __align__(16) ULL  AsD[2][16][128];   // 32KB, duplicated pairs
    __shared__ __align__(16) float Bs[2][16][128];   // 16KB
    int tid = threadIdx.x;
    int bm = blockIdx.y * 128;
    int bn = blockIdx.x * 128;
    int kOff = SPLIT ? blockIdx.z * Kblk : 0;
    if (SPLIT) C += (size_t)blockIdx.z * M * N;
    int tx = tid & 15, ty = tid >> 4;
    const int KT = Kblk >> 4;

    ULL acc[8][4];
    #pragma unroll
    for (int m = 0; m < 8; m++)
        #pragma unroll
        for (int j = 0; j < 4; j++) acc[m][j] = 0ULL;

    float4 pa[2], pb[2];
    auto loadG = [&](int kt){
        #pragma unroll
        for (int i = 0; i < 2; i++){
            int v = tid + i*256;
            int row = v >> 2, kq = (v & 3) * 4;
            pa[i] = *(const float4*)&A[(size_t)(bm + row)*Ktot + kOff + kt*16 + kq];
            int brow = v >> 5, bc = (v & 31) * 4;
            pb[i] = *(const float4*)&B[(size_t)(kOff + kt*16 + brow)*N + bn + bc];
        }
    };
    auto storeS = [&](int buf){
        #pragma unroll
        for (int i = 0; i < 2; i++){
            int v = tid + i*256;
            int row = v >> 2, kq = (v & 3) * 4;
            AsD[buf][kq+0][row] = dup2(pa[i].x);
            AsD[buf][kq+1][row] = dup2(pa[i].y);
            AsD[buf][kq+2][row] = dup2(pa[i].z);
            AsD[buf][kq+3][row] = dup2(pa[i].w);
            int brow = v >> 5, bc = (v & 31) * 4;
            *(float4*)&Bs[buf][brow][bc] = pb[i];
        }
    };

    loadG(0);
    storeS(0);
    __syncthreads();

    for (int kt = 0; kt < KT; kt++){
        int cur = kt & 1;
        if (kt + 1 < KT) loadG(kt + 1);
        #pragma unroll
        for (int k = 0; k < 16; k++){
            ULL ad[8];
            #pragma unroll
            for (int u = 0; u < 8; u++) ad[u] = AsD[cur][k][ty*8 + u];
            ULL bp[4];
            #pragma unroll
            for (int j = 0; j < 4; j++)
                bp[j] = *(const ULL*)&Bs[cur][k][tx*8 + 2*j];
            #pragma unroll
            for (int m = 0; m < 8; m++)
                #pragma unroll
                for (int j = 0; j < 4; j++)
                    fma2(acc[m][j], ad[m], bp[j]);
        }
        if (kt + 1 < KT) storeS(1 - cur);
        __syncthreads();
    }

    #pragma unroll
    for (int m = 0; m < 8; m++){
        int row = bm + ty*8 + m;
        #pragma unroll
        for (int j = 0; j < 4; j++){
            int col = bn + tx*8 + 2*j;
            float2 v = unpack2(acc[m][j]);
            if (EPI & 1){ v.x += bias[col]; v.y += bias[col+1]; }
            if (EPI & 2){ v.x += res[(size_t)row*N + col]; v.y += res[(size_t)row*N + col + 1]; }
            if (EPI & 4){ v.x = fmaxf(v.x, 0.f); v.y = fmaxf(v.y, 0.f); }
            *(float2*)&C[(size_t)row*N + col] = v;
        }
    }
}

// ------------- kRLN: split-K(4) reduce + bias0 + LN2, one row per block ----------
// Reproduces R2's kReduce<1> sum order (z ascending, then bias) and kLN tree.
__global__ void kRLN(const float* __restrict__ g2, const float* __restrict__ b2){
    __shared__ float red[256];
    int r = blockIdx.x;
    int t = threadIdx.x;
    const size_t MN = (size_t)NC*DD;
    size_t idx = (size_t)r*DD + t;
    float a = g_part[idx];
    a += g_part[MN + idx];
    a += g_part[2*MN + idx];
    a += g_part[3*MN + idx];
    a += g_bias0[t];
    g_x0[idx] = a;
    float mean = blockReduceSum256(a, red) * (1.f/DD);
    float dx = a - mean;
    float var = blockReduceSum256(dx*dx, red) * (1.f/DD);
    g_h2[idx] = dx * rsqrtf(var + 1e-5f) * g2[t] + b2[t];
}

// ---------------- split-K reduce + epilogue (elementwise) ----------------
template<int EPI>
__global__ void kReduce(const float* __restrict__ part, const float* __restrict__ bias,
                        const float* __restrict__ res, float* __restrict__ C,
                        int MN4, int N, int S){
    int v = blockIdx.x * 256 + threadIdx.x;
    if (v >= MN4) return;
    const float4* P = (const float4*)part;
    float4 a = P[v];
    for (int z = 1; z < S; z++){
        float4 p = P[(size_t)z*MN4 + v];
        a.x += p.x; a.y += p.y; a.z += p.z; a.w += p.w;
    }
    if (EPI & 1){
        int col = (v*4) & (N-1);
        float4 bb = *(const float4*)&bias[col];
        a.x += bb.x; a.y += bb.y; a.z += bb.z; a.w += bb.w;
    }
    if (EPI & 2){
        float4 r = ((const float4*)res)[v];
        a.x += r.x; a.y += r.y; a.z += r.z; a.w += r.w;
    }
    if (EPI & 4){
        a.x = fmaxf(a.x, 0.f); a.y = fmaxf(a.y, 0.f);
        a.z = fmaxf(a.z, 0.f); a.w = fmaxf(a.w, 0.f);
    }
    ((float4*)C)[v] = a;
}

// -------- kRZ: split-K(4) reduce + be1 + relu + logit + lstar per (b,i) ----------
// Logit dot replicates R2's kZ exactly: warp per length, lane-strided ascending
// sum, shfl_down tree.
__global__ void kRZ(const float* __restrict__ be1, const float* __restrict__ We2,
                    const float* __restrict__ be2){
    __shared__ float logit[LL];
    int blk = blockIdx.x;
    int t = threadIdx.x;
    int w = t >> 5, lane = t & 31;
    const size_t MN = (size_t)NC*DD;
    size_t rowOff = (size_t)(blk*LL + w)*DD;
    float s = 0.f;
    #pragma unroll
    for (int j = 0; j < 8; j++){
        int d = lane + 32*j;
        size_t idx = rowOff + d;
        float a = g_part[idx];
        a += g_part[MN + idx];
        a += g_part[2*MN + idx];
        a += g_part[3*MN + idx];
        a += be1[d];
        s += fmaxf(a, 0.f) * We2[d];
    }
    #pragma unroll
    for (int o = 16; o; o >>= 1) s += __shfl_down_sync(0xffffffffu, s, o);
    if (lane == 0) logit[w] = s + be2[0];
    __syncthreads();
    if (t == 0){
        int i = blk & 127;
        int lmax = TT - i; if (lmax > LL) lmax = LL;
        int lstar = lmax;
        for (int l = 1; l <= lmax; l++){
            if (logit[l-1] > 0.f){ lstar = l; break; }
        }
        g_lstar[blk] = lstar;
    }
}

// ---------------- chain resolution + output ----------------
__global__ void kChain(){
    int b = threadIdx.x;
    if (b < BB){
        int i = 0, cnt = 0;
        for (int s = 0; s < TT; s++){
            if (i < TT){
                int ls = g_lstar[b*TT + i];
                g_slot[b*TT + s] = (b*TT + i)*LL + (ls - 1);
                i += ls;
                cnt++;
            } else g_slot[b*TT + s] = -1;
        }
        g_cnt[b] = cnt;
    }
}

__global__ void kOut(float* __restrict__ out, int out_size){
    int r = blockIdx.x;
    int t = threadIdx.x;
    int c = g_slot[r];
    out[(size_t)r*DD + t] = (c >= 0) ? g_enc[(size_t)c*DD + t] : 0.f;
    if (r == 0 && t < BB && out_size > BB*TT*DD + t)
        out[BB*TT*DD + t] = (float)g_cnt[t];
}

// ---------------- launch ----------------
extern "C" void kernel_launch(void* const* d_in, const int* in_sizes, int n_in,
                              void* d_out, int out_size){
    const float* frames = (const float*)d_in[0];
    const float* cls    = (const float*)d_in[1];
    const float* Wq  = (const float*)d_in[2];  const float* bq  = (const float*)d_in[3];
    const float* Wk  = (const float*)d_in[4];  const float* bk  = (const float*)d_in[5];
    const float* Wv  = (const float*)d_in[6];  const float* bv  = (const float*)d_in[7];
    const float* Wo  = (const float*)d_in[8];  const float* bo  = (const float*)d_in[9];
    const float* ln1g= (const float*)d_in[10]; const float* ln1b= (const float*)d_in[11];
    const float* ln2g= (const float*)d_in[12]; const float* ln2b= (const float*)d_in[13];
    const float* W1  = (const float*)d_in[14]; const float* b1f = (const float*)d_in[15];
    const float* W2  = (const float*)d_in[16]; const float* b2f = (const float*)d_in[17];
    const float* We1 = (const float*)d_in[18]; const float* be1 = (const float*)d_in[19];
    const float* We2 = (const float*)d_in[20]; const float* be2 = (const float*)d_in[21];
    float* out = (float*)d_out;

    float *p_o0, *p_x0, *p_h2, *p_u, *p_enc, *p_part;
    cudaGetSymbolAddress((void**)&p_o0,   g_o0);
    cudaGetSymbolAddress((void**)&p_x0,   g_x0);
    cudaGetSymbolAddress((void**)&p_h2,   g_h2);
    cudaGetSymbolAddress((void**)&p_u,    g_u);
    cudaGetSymbolAddress((void**)&p_enc,  g_enc);
    cudaGetSymbolAddress((void**)&p_part, g_part);

    const int MN4 = NC*DD/4;
    const int RB  = MN4/256;

    kC<<<1, 256>>>(cls, Wq, bq, Wk, bk, Wv, bv, bo, ln1g, ln1b);
    kP<<<BT/4, 256>>>(frames, Wk, bk, Wv, bv, ln1g, ln1b);
    kA<<<BT, 256>>>();

    // GEMM1 partials: o0 @ Wo   [split-K=4]
    sgemm128<0, true><<<dim3(DD/128, NC/128, 4), 256>>>(p_o0, Wo, nullptr, nullptr, p_part, NC, DD, 64, DD);
    // x0 = partials + (cls+bo); h2 = LN2(x0)   [fused]
    kRLN<<<NC, 256>>>(ln2g, ln2b);
    // u = relu(h2 @ W1 + b1f)
    sgemm128<5, false><<<dim3(FF/128, NC/128, 1), 256>>>(p_h2, W1, b1f, nullptr, p_u, NC, FF, DD, DD);
    // enc = u @ W2 + b2f + x0   [split-K=8]
    sgemm128<0, true><<<dim3(DD/128, NC/128, 8), 256>>>(p_u, W2, nullptr, nullptr, p_part, NC, DD, 256, FF);
    kReduce<3><<<RB, 256>>>(p_part, b2f, p_x0, p_enc, MN4, DD, 8);
    // GEMM4 partials: enc @ We1   [split-K=4]
    sgemm128<0, true><<<dim3(DD/128, NC/128, 4), 256>>>(p_enc, We1, nullptr, nullptr, p_part, NC, DD, 64, DD);
    // fused reduce + relu + logit + lstar
    kRZ<<<BT, 256>>>(be1, We2, be2);

    kChain<<<1, 32>>>();
    kOut<<<BT, 256>>>(out, out_size);
}

// round 5
// speedup vs baseline: 1.1007x; 1.1007x over previous
#include <cuda_runtime.h>
#include <math.h>

#define DD  256
#define TT  128
#define BB  2
#define BT  256
#define LL  8
#define HH  4
#define DHH 64
#define FF  2048
#define NC  2048

typedef unsigned long long ULL;

// ---------------- device scratch ----------------
__device__ float g_qcls[DD];
__device__ float g_vcls[DD];
__device__ float g_scls[HH];
__device__ float g_bias0[DD];      // cls_token + bo
__device__ float g_kf[BT*DD];
__device__ float g_vf[BT*DD];
__device__ float g_sf[BT*HH];
__device__ float g_o0[NC*DD];
__device__ float g_x0[NC*DD];
__device__ float g_h2[NC*DD];
__device__ float g_u [NC*FF];
__device__ float g_enc[NC*DD];
__device__ float g_part[8*NC*DD];
__device__ int   g_lstar[BT];
__device__ int   g_slot[BB*TT];
__device__ int   g_cnt[BB];

// ---------------- f32x2 helpers ----------------
__device__ __forceinline__ ULL dup2(float x){
    ULL r; unsigned u = __float_as_uint(x);
    asm("mov.b64 %0, {%1, %1};" : "=l"(r) : "r"(u));
    return r;
}
__device__ __forceinline__ void fma2(ULL &c, ULL a, ULL b){
    asm("fma.rn.f32x2 %0, %1, %2, %0;" : "+l"(c) : "l"(a), "l"(b));
}
__device__ __forceinline__ float2 unpack2(ULL p){
    unsigned lo, hi;
    asm("mov.b64 {%0, %1}, %2;" : "=r"(lo), "=r"(hi) : "l"(p));
    return make_float2(__uint_as_float(lo), __uint_as_float(hi));
}

__device__ __forceinline__ float blockReduceSum256(float v, float* red){
    int t = threadIdx.x;
    red[t] = v; __syncthreads();
    #pragma unroll
    for (int s = 128; s > 0; s >>= 1){
        if (t < s) red[t] += red[t + s];
        __syncthreads();
    }
    float r = red[0];
    __syncthreads();
    return r;
}

// ---------------- kernel C: CLS precompute (1 block) ----------------
__global__ void kC(const float* __restrict__ cls,
                   const float* __restrict__ Wq, const float* __restrict__ bq,
                   const float* __restrict__ Wk, const float* __restrict__ bk,
                   const float* __restrict__ Wv, const float* __restrict__ bv,
                   const float* __restrict__ bo,
                   const float* __restrict__ g1, const float* __restrict__ b1){
    __shared__ float red[256];
    __shared__ float h[DD];
    int t = threadIdx.x;
    float x = cls[t];
    float mean = blockReduceSum256(x, red) * (1.f/DD);
    float dx = x - mean;
    float var = blockReduceSum256(dx*dx, red) * (1.f/DD);
    float hn = dx * rsqrtf(var + 1e-5f) * g1[t] + b1[t];
    h[t] = hn; __syncthreads();

    float q = bq[t], k = bk[t], v = bv[t];
    #pragma unroll 8
    for (int j = 0; j < DD; j++){
        float hj = h[j];
        q += hj * Wq[j*DD + t];
        k += hj * Wk[j*DD + t];
        v += hj * Wv[j*DD + t];
    }
    g_qcls[t] = q;
    g_vcls[t] = v;
    g_bias0[t] = cls[t] + bo[t];

    red[t] = q * k; __syncthreads();
    if (t < HH){
        float s = 0.f;
        #pragma unroll
        for (int d = 0; d < DHH; d++) s += red[t*DHH + d];
        g_scls[t] = s * 0.125f;
    }
}

// ---------------- kernel P: per-frame LN1 + K/V + score, 4 frames/block ----------
__global__ void kP(const float* __restrict__ frames,
                   const float* __restrict__ Wk, const float* __restrict__ bk,
                   const float* __restrict__ Wv, const float* __restrict__ bv,
                   const float* __restrict__ g1, const float* __restrict__ b1){
    __shared__ float red[256];
    __shared__ float hs[4][DD];
    int blk = blockIdx.x;
    int t = threadIdx.x;
    #pragma unroll
    for (int f = 0; f < 4; f++){
        float x = frames[(blk*4 + f)*DD + t];
        float mean = blockReduceSum256(x, red) * (1.f/DD);
        float dx = x - mean;
        float var = blockReduceSum256(dx*dx, red) * (1.f/DD);
        hs[f][t] = dx * rsqrtf(var + 1e-5f) * g1[t] + b1[t];
    }
    __syncthreads();

    float kk[4], vv[4];
    #pragma unroll
    for (int f = 0; f < 4; f++){ kk[f] = bk[t]; vv[f] = bv[t]; }
    #pragma unroll 4
    for (int j = 0; j < DD; j++){
        float wk = Wk[j*DD + t], wv = Wv[j*DD + t];
        #pragma unroll
        for (int f = 0; f < 4; f++){
            kk[f] += hs[f][j] * wk;
            vv[f] += hs[f][j] * wv;
        }
    }
    #pragma unroll
    for (int f = 0; f < 4; f++){
        g_kf[(blk*4 + f)*DD + t] = kk[f];
        g_vf[(blk*4 + f)*DD + t] = vv[f];
    }
    float qc = g_qcls[t];
    #pragma unroll
    for (int f = 0; f < 4; f++){
        red[t] = qc * kk[f]; __syncthreads();
        if (t < HH){
            float s = 0.f;
            #pragma unroll
            for (int d = 0; d < DHH; d++) s += red[t*DHH + d];
            g_sf[(blk*4 + f)*HH + t] = s * 0.125f;
        }
        __syncthreads();
    }
}

// ---------------- kernel A: attention (CLS query) for all 8 lengths ----------
__global__ void kA(){
    __shared__ float vsh[9][DD];
    __shared__ float sh_s[HH][9];
    __shared__ float wsh[LL][HH][9];
    int blk = blockIdx.x;
    int b = blk >> 7;
    int i = blk & 127;
    int t = threadIdx.x;

    vsh[0][t] = g_vcls[t];
    #pragma unroll
    for (int tt = 0; tt < 8; tt++)
        vsh[tt+1][t] = (i + tt < TT) ? g_vf[(b*TT + i + tt)*DD + t] : 0.f;

    if (t < 36){
        int hh = t / 9, idx = t % 9;
        float s;
        if (idx == 0) s = g_scls[hh];
        else {
            int tt = idx - 1;
            s = (i + tt < TT) ? g_sf[(b*TT + i + tt)*HH + hh] : -1e30f;
        }
        sh_s[hh][idx] = s;
    }
    __syncthreads();

    if (t < 32){
        int l  = (t >> 2) + 1;
        int hh = t & 3;
        float m = sh_s[hh][0];
        for (int tt = 0; tt < l; tt++)
            if (i + tt < TT) m = fmaxf(m, sh_s[hh][tt+1]);
        float e0 = expf(sh_s[hh][0] - m);
        float sum = e0;
        float e[8];
        #pragma unroll
        for (int tt = 0; tt < 8; tt++){
            bool inc = (tt < l) && (i + tt < TT);
            e[tt] = inc ? expf(sh_s[hh][tt+1] - m) : 0.f;
            sum += e[tt];
        }
        float inv = 1.f / sum;
        wsh[l-1][hh][0] = e0 * inv;
        #pragma unroll
        for (int tt = 0; tt < 8; tt++) wsh[l-1][hh][tt+1] = e[tt] * inv;
    }
    __syncthreads();

    int hd = t >> 6;
    #pragma unroll
    for (int l = 0; l < LL; l++){
        float acc = wsh[l][hd][0] * vsh[0][t];
        #pragma unroll
        for (int tt = 0; tt < 8; tt++)
            acc += wsh[l][hd][tt+1] * vsh[tt+1][t];
        g_o0[(blk*LL + l)*DD + t] = acc;
    }
}

// ------- f32x2 SGEMM: 128(M)x64(N) tile, M-paired accumulators, no inner MOVs ----
// acc[mp][j] = (C[r0][col], C[r0+1][col]); A pairs are native LDS.128 from As[k][m];
// B stored pre-duplicated (BsD) at smem-store time; B frag cols strided by 16
// (conflict-free LDS.64). EPI bit0=+bias[col], bit1=+res, bit2=relu.
template<int EPI, bool SPLIT>
__global__ __launch_bounds__(256, 3)
void sgemmMN(const float* __restrict__ A, const float* __restrict__ B,
             const float* __restrict__ bias, const float* __restrict__ res,
             float* __restrict__ C, int M, int N, int Kblk, int Ktot){
    __shared__ __align__(16) float As[2][16][132];  // padded rows (bank spread)
    __shared__ __align__(16) ULL  BsD[2][16][64];
    int tid = threadIdx.x;
    int bm = blockIdx.y * 128;
    int bn = blockIdx.x * 64;
    int kOff = SPLIT ? blockIdx.z * Kblk : 0;
    if (SPLIT) C += (size_t)blockIdx.z * M * N;
    int tx = tid & 15, ty = tid >> 4;
    const int KT = Kblk >> 4;

    ULL acc[4][4];
    #pragma unroll
    for (int mp = 0; mp < 4; mp++)
        #pragma unroll
        for (int j = 0; j < 4; j++) acc[mp][j] = 0ULL;

    float4 pa[2], pb;
    auto loadG = [&](int kt){
        #pragma unroll
        for (int i = 0; i < 2; i++){
            int v = tid + i*256;
            int row = v >> 2, kq = (v & 3) * 4;
            pa[i] = *(const float4*)&A[(size_t)(bm + row)*Ktot + kOff + kt*16 + kq];
        }
        int brow = tid >> 4, bc = (tid & 15) * 4;
        pb = *(const float4*)&B[(size_t)(kOff + kt*16 + brow)*N + bn + bc];
    };
    auto storeS = [&](int buf){
        #pragma unroll
        for (int i = 0; i < 2; i++){
            int v = tid + i*256;
            int row = v >> 2, kq = (v & 3) * 4;
            As[buf][kq+0][row] = pa[i].x;
            As[buf][kq+1][row] = pa[i].y;
            As[buf][kq+2][row] = pa[i].z;
            As[buf][kq+3][row] = pa[i].w;
        }
        int brow = tid >> 4, bc = (tid & 15) * 4;
        BsD[buf][brow][bc+0] = dup2(pb.x);
        BsD[buf][brow][bc+1] = dup2(pb.y);
        BsD[buf][brow][bc+2] = dup2(pb.z);
        BsD[buf][brow][bc+3] = dup2(pb.w);
    };

    loadG(0);
    storeS(0);
    __syncthreads();

    for (int kt = 0; kt < KT; kt++){
        int cur = kt & 1;
        if (kt + 1 < KT) loadG(kt + 1);
        #pragma unroll
        for (int k = 0; k < 16; k++){
            ulonglong2 a01 = *(const ulonglong2*)&As[cur][k][ty*8];
            ulonglong2 a23 = *(const ulonglong2*)&As[cur][k][ty*8 + 4];
            ULL am0 = a01.x, am1 = a01.y, am2 = a23.x, am3 = a23.y;
            ULL bd[4];
            #pragma unroll
            for (int j = 0; j < 4; j++) bd[j] = BsD[cur][k][tx + 16*j];
            #pragma unroll
            for (int j = 0; j < 4; j++){
                fma2(acc[0][j], am0, bd[j]);
                fma2(acc[1][j], am1, bd[j]);
                fma2(acc[2][j], am2, bd[j]);
                fma2(acc[3][j], am3, bd[j]);
            }
        }
        if (kt + 1 < KT) storeS(1 - cur);
        __syncthreads();
    }

    #pragma unroll
    for (int mp = 0; mp < 4; mp++){
        int r0 = bm + ty*8 + 2*mp;
        #pragma unroll
        for (int j = 0; j < 4; j++){
            int col = bn + tx + 16*j;
            float2 v = unpack2(acc[mp][j]);   // v.x -> row r0, v.y -> row r0+1
            float o0 = v.x, o1 = v.y;
            if (EPI & 1){ float bx = bias[col]; o0 += bx; o1 += bx; }
            if (EPI & 2){
                o0 += res[(size_t)r0*N + col];
                o1 += res[(size_t)(r0+1)*N + col];
            }
            if (EPI & 4){ o0 = fmaxf(o0, 0.f); o1 = fmaxf(o1, 0.f); }
            C[(size_t)r0*N + col]     = o0;
            C[(size_t)(r0+1)*N + col] = o1;
        }
    }
}

// ------------- kRLN: split-K(4) reduce + bias0 + LN2, one row per block ----------
__global__ void kRLN(const float* __restrict__ g2, const float* __restrict__ b2){
    __shared__ float red[256];
    int r = blockIdx.x;
    int t = threadIdx.x;
    const size_t MN = (size_t)NC*DD;
    size_t idx = (size_t)r*DD + t;
    float a = g_part[idx];
    a += g_part[MN + idx];
    a += g_part[2*MN + idx];
    a += g_part[3*MN + idx];
    a += g_bias0[t];
    g_x0[idx] = a;
    float mean = blockReduceSum256(a, red) * (1.f/DD);
    float dx = a - mean;
    float var = blockReduceSum256(dx*dx, red) * (1.f/DD);
    g_h2[idx] = dx * rsqrtf(var + 1e-5f) * g2[t] + b2[t];
}

// ---------------- split-K reduce + epilogue (elementwise) ----------------
template<int EPI>
__global__ void kReduce(const float* __restrict__ part, const float* __restrict__ bias,
                        const float* __restrict__ res, float* __restrict__ C,
                        int MN4, int N, int S){
    int v = blockIdx.x * 256 + threadIdx.x;
    if (v >= MN4) return;
    const float4* P = (const float4*)part;
    float4 a = P[v];
    for (int z = 1; z < S; z++){
        float4 p = P[(size_t)z*MN4 + v];
        a.x += p.x; a.y += p.y; a.z += p.z; a.w += p.w;
    }
    if (EPI & 1){
        int col = (v*4) & (N-1);
        float4 bb = *(const float4*)&bias[col];
        a.x += bb.x; a.y += bb.y; a.z += bb.z; a.w += bb.w;
    }
    if (EPI & 2){
        float4 r = ((const float4*)res)[v];
        a.x += r.x; a.y += r.y; a.z += r.z; a.w += r.w;
    }
    if (EPI & 4){
        a.x = fmaxf(a.x, 0.f); a.y = fmaxf(a.y, 0.f);
        a.z = fmaxf(a.z, 0.f); a.w = fmaxf(a.w, 0.f);
    }
    ((float4*)C)[v] = a;
}

// -------- kRZ: split-K(4) reduce + be1 + relu + logit + lstar per (b,i) ----------
__global__ void kRZ(const float* __restrict__ be1, const float* __restrict__ We2,
                    const float* __restrict__ be2){
    __shared__ float logit[LL];
    int blk = blockIdx.x;
    int t = threadIdx.x;
    int w = t >> 5, lane = t & 31;
    const size_t MN = (size_t)NC*DD;
    size_t rowOff = (size_t)(blk*LL + w)*DD;
    float s = 0.f;
    #pragma unroll
    for (int j = 0; j < 8; j++){
        int d = lane + 32*j;
        size_t idx = rowOff + d;
        float a = g_part[idx];
        a += g_part[MN + idx];
        a += g_part[2*MN + idx];
        a += g_part[3*MN + idx];
        a += be1[d];
        s += fmaxf(a, 0.f) * We2[d];
    }
    #pragma unroll
    for (int o = 16; o; o >>= 1) s += __shfl_down_sync(0xffffffffu, s, o);
    if (lane == 0) logit[w] = s + be2[0];
    __syncthreads();
    if (t == 0){
        int i = blk & 127;
        int lmax = TT - i; if (lmax > LL) lmax = LL;
        int lstar = lmax;
        for (int l = 1; l <= lmax; l++){
            if (logit[l-1] > 0.f){ lstar = l; break; }
        }
        g_lstar[blk] = lstar;
    }
}

// ---------------- chain resolution + output ----------------
__global__ void kChain(){
    int b = threadIdx.x;
    if (b < BB){
        int i = 0, cnt = 0;
        for (int s = 0; s < TT; s++){
            if (i < TT){
                int ls = g_lstar[b*TT + i];
                g_slot[b*TT + s] = (b*TT + i)*LL + (ls - 1);
                i += ls;
                cnt++;
            } else g_slot[b*TT + s] = -1;
        }
        g_cnt[b] = cnt;
    }
}

__global__ void kOut(float* __restrict__ out, int out_size){
    int r = blockIdx.x;
    int t = threadIdx.x;
    int c = g_slot[r];
    out[(size_t)r*DD + t] = (c >= 0) ? g_enc[(size_t)c*DD + t] : 0.f;
    if (r == 0 && t < BB && out_size > BB*TT*DD + t)
        out[BB*TT*DD + t] = (float)g_cnt[t];
}

// ---------------- launch ----------------
extern "C" void kernel_launch(void* const* d_in, const int* in_sizes, int n_in,
                              void* d_out, int out_size){
    const float* frames = (const float*)d_in[0];
    const float* cls    = (const float*)d_in[1];
    const float* Wq  = (const float*)d_in[2];  const float* bq  = (const float*)d_in[3];
    const float* Wk  = (const float*)d_in[4];  const float* bk  = (const float*)d_in[5];
    const float* Wv  = (const float*)d_in[6];  const float* bv  = (const float*)d_in[7];
    const float* Wo  = (const float*)d_in[8];  const float* bo  = (const float*)d_in[9];
    const float* ln1g= (const float*)d_in[10]; const float* ln1b= (const float*)d_in[11];
    const float* ln2g= (const float*)d_in[12]; const float* ln2b= (const float*)d_in[13];
    const float* W1  = (const float*)d_in[14]; const float* b1f = (const float*)d_in[15];
    const float* W2  = (const float*)d_in[16]; const float* b2f = (const float*)d_in[17];
    const float* We1 = (const float*)d_in[18]; const float* be1 = (const float*)d_in[19];
    const float* We2 = (const float*)d_in[20]; const float* be2 = (const float*)d_in[21];
    float* out = (float*)d_out;

    float *p_o0, *p_x0, *p_h2, *p_u, *p_enc, *p_part;
    cudaGetSymbolAddress((void**)&p_o0,   g_o0);
    cudaGetSymbolAddress((void**)&p_x0,   g_x0);
    cudaGetSymbolAddress((void**)&p_h2,   g_h2);
    cudaGetSymbolAddress((void**)&p_u,    g_u);
    cudaGetSymbolAddress((void**)&p_enc,  g_enc);
    cudaGetSymbolAddress((void**)&p_part, g_part);

    const int MN4 = NC*DD/4;
    const int RB  = MN4/256;

    kC<<<1, 256>>>(cls, Wq, bq, Wk, bk, Wv, bv, bo, ln1g, ln1b);
    kP<<<BT/4, 256>>>(frames, Wk, bk, Wv, bv, ln1g, ln1b);
    kA<<<BT, 256>>>();

    // GEMM1 partials: o0 @ Wo   [split-K=4, Kblk=64]
    sgemmMN<0, true><<<dim3(DD/64, NC/128, 4), 256>>>(p_o0, Wo, nullptr, nullptr, p_part, NC, DD, 64, DD);
    // x0 = partials + (cls+bo); h2 = LN2(x0)   [fused]
    kRLN<<<NC, 256>>>(ln2g, ln2b);
    // u = relu(h2 @ W1 + b1f)
    sgemmMN<5, false><<<dim3(FF/64, NC/128, 1), 256>>>(p_h2, W1, b1f, nullptr, p_u, NC, FF, DD, DD);
    // enc = u @ W2 + b2f + x0   [split-K=8, Kblk=256]
    sgemmMN<0, true><<<dim3(DD/64, NC/128, 8), 256>>>(p_u, W2, nullptr, nullptr, p_part, NC, DD, 256, FF);
    kReduce<3><<<RB, 256>>>(p_part, b2f, p_x0, p_enc, MN4, DD, 8);
    // GEMM4 partials: enc @ We1   [split-K=4, Kblk=64]
    sgemmMN<0, true><<<dim3(DD/64, NC/128, 4), 256>>>(p_enc, We1, nullptr, nullptr, p_part, NC, DD, 64, DD);
    // fused reduce + relu + logit + lstar
    kRZ<<<BT, 256>>>(be1, We2, be2);

    kChain<<<1, 32>>>();
    kOut<<<BT, 256>>>(out, out_size);
}

// round 6
// speedup vs baseline: 1.2305x; 1.1180x over previous
#include <cuda_runtime.h>
#include <math.h>

#define DD  256
#define TT  128
#define BB  2
#define BT  256
#define LL  8
#define HH  4
#define DHH 64
#define FF  2048
#define NC  2048

typedef unsigned long long ULL;

// ---------------- device scratch ----------------
__device__ float g_qcls[DD];
__device__ float g_vcls[DD];
__device__ float g_scls[HH];
__device__ float g_bias0[DD];      // cls_token + bo
__device__ float g_kf[BT*DD];
__device__ float g_vf[BT*DD];
__device__ float g_sf[BT*HH];
__device__ float g_o0[NC*DD];
__device__ float g_x0[NC*DD];
__device__ float g_h2[NC*DD];
__device__ float g_u [NC*FF];
__device__ float g_enc[NC*DD];
__device__ float g_part[8*NC*DD];
__device__ int   g_lstar[BT];
__device__ int   g_slot[BB*TT];
__device__ int   g_cnt[BB];

// ---------------- f32x2 helpers ----------------
__device__ __forceinline__ ULL dup2(float x){
    ULL r; unsigned u = __float_as_uint(x);
    asm("mov.b64 %0, {%1, %1};" : "=l"(r) : "r"(u));
    return r;
}
__device__ __forceinline__ void fma2(ULL &c, ULL a, ULL b){
    asm("fma.rn.f32x2 %0, %1, %2, %0;" : "+l"(c) : "l"(a), "l"(b));
}
__device__ __forceinline__ float2 unpack2(ULL p){
    unsigned lo, hi;
    asm("mov.b64 {%0, %1}, %2;" : "=r"(lo), "=r"(hi) : "l"(p));
    return make_float2(__uint_as_float(lo), __uint_as_float(hi));
}

__device__ __forceinline__ float blockReduceSum256(float v, float* red){
    int t = threadIdx.x;
    red[t] = v; __syncthreads();
    #pragma unroll
    for (int s = 128; s > 0; s >>= 1){
        if (t < s) red[t] += red[t + s];
        __syncthreads();
    }
    float r = red[0];
    __syncthreads();
    return r;
}

// ---------------- kernel C: CLS precompute (1 block) ----------------
__global__ void kC(const float* __restrict__ cls,
                   const float* __restrict__ Wq, const float* __restrict__ bq,
                   const float* __restrict__ Wk, const float* __restrict__ bk,
                   const float* __restrict__ Wv, const float* __restrict__ bv,
                   const float* __restrict__ bo,
                   const float* __restrict__ g1, const float* __restrict__ b1){
    __shared__ float red[256];
    __shared__ float h[DD];
    int t = threadIdx.x;
    float x = cls[t];
    float mean = blockReduceSum256(x, red) * (1.f/DD);
    float dx = x - mean;
    float var = blockReduceSum256(dx*dx, red) * (1.f/DD);
    float hn = dx * rsqrtf(var + 1e-5f) * g1[t] + b1[t];
    h[t] = hn; __syncthreads();

    float q = bq[t], k = bk[t], v = bv[t];
    #pragma unroll 8
    for (int j = 0; j < DD; j++){
        float hj = h[j];
        q += hj * Wq[j*DD + t];
        k += hj * Wk[j*DD + t];
        v += hj * Wv[j*DD + t];
    }
    g_qcls[t] = q;
    g_vcls[t] = v;
    g_bias0[t] = cls[t] + bo[t];

    red[t] = q * k; __syncthreads();
    if (t < HH){
        float s = 0.f;
        #pragma unroll
        for (int d = 0; d < DHH; d++) s += red[t*DHH + d];
        g_scls[t] = s * 0.125f;
    }
}

// ---------------- kernel P: per-frame LN1 + K/V + score, 4 frames/block ----------
__global__ void kP(const float* __restrict__ frames,
                   const float* __restrict__ Wk, const float* __restrict__ bk,
                   const float* __restrict__ Wv, const float* __restrict__ bv,
                   const float* __restrict__ g1, const float* __restrict__ b1){
    __shared__ float red[256];
    __shared__ float hs[4][DD];
    int blk = blockIdx.x;
    int t = threadIdx.x;
    #pragma unroll
    for (int f = 0; f < 4; f++){
        float x = frames[(blk*4 + f)*DD + t];
        float mean = blockReduceSum256(x, red) * (1.f/DD);
        float dx = x - mean;
        float var = blockReduceSum256(dx*dx, red) * (1.f/DD);
        hs[f][t] = dx * rsqrtf(var + 1e-5f) * g1[t] + b1[t];
    }
    __syncthreads();

    float kk[4], vv[4];
    #pragma unroll
    for (int f = 0; f < 4; f++){ kk[f] = bk[t]; vv[f] = bv[t]; }
    #pragma unroll 4
    for (int j = 0; j < DD; j++){
        float wk = Wk[j*DD + t], wv = Wv[j*DD + t];
        #pragma unroll
        for (int f = 0; f < 4; f++){
            kk[f] += hs[f][j] * wk;
            vv[f] += hs[f][j] * wv;
        }
    }
    #pragma unroll
    for (int f = 0; f < 4; f++){
        g_kf[(blk*4 + f)*DD + t] = kk[f];
        g_vf[(blk*4 + f)*DD + t] = vv[f];
    }
    float qc = g_qcls[t];
    #pragma unroll
    for (int f = 0; f < 4; f++){
        red[t] = qc * kk[f]; __syncthreads();
        if (t < HH){
            float s = 0.f;
            #pragma unroll
            for (int d = 0; d < DHH; d++) s += red[t*DHH + d];
            g_sf[(blk*4 + f)*HH + t] = s * 0.125f;
        }
        __syncthreads();
    }
}

// ---------------- kernel A: attention (CLS query) for all 8 lengths ----------
__global__ void kA(){
    __shared__ float vsh[9][DD];
    __shared__ float sh_s[HH][9];
    __shared__ float wsh[LL][HH][9];
    int blk = blockIdx.x;
    int b = blk >> 7;
    int i = blk & 127;
    int t = threadIdx.x;

    vsh[0][t] = g_vcls[t];
    #pragma unroll
    for (int tt = 0; tt < 8; tt++)
        vsh[tt+1][t] = (i + tt < TT) ? g_vf[(b*TT + i + tt)*DD + t] : 0.f;

    if (t < 36){
        int hh = t / 9, idx = t % 9;
        float s;
        if (idx == 0) s = g_scls[hh];
        else {
            int tt = idx - 1;
            s = (i + tt < TT) ? g_sf[(b*TT + i + tt)*HH + hh] : -1e30f;
        }
        sh_s[hh][idx] = s;
    }
    __syncthreads();

    if (t < 32){
        int l  = (t >> 2) + 1;
        int hh = t & 3;
        float m = sh_s[hh][0];
        for (int tt = 0; tt < l; tt++)
            if (i + tt < TT) m = fmaxf(m, sh_s[hh][tt+1]);
        float e0 = expf(sh_s[hh][0] - m);
        float sum = e0;
        float e[8];
        #pragma unroll
        for (int tt = 0; tt < 8; tt++){
            bool inc = (tt < l) && (i + tt < TT);
            e[tt] = inc ? expf(sh_s[hh][tt+1] - m) : 0.f;
            sum += e[tt];
        }
        float inv = 1.f / sum;
        wsh[l-1][hh][0] = e0 * inv;
        #pragma unroll
        for (int tt = 0; tt < 8; tt++) wsh[l-1][hh][tt+1] = e[tt] * inv;
    }
    __syncthreads();

    int hd = t >> 6;
    #pragma unroll
    for (int l = 0; l < LL; l++){
        float acc = wsh[l][hd][0] * vsh[0][t];
        #pragma unroll
        for (int tt = 0; tt < 8; tt++)
            acc += wsh[l][hd][tt+1] * vsh[tt+1][t];
        g_o0[(blk*LL + l)*DD + t] = acc;
    }
}

// ------- narrow f32x2 SGEMM: 128(M)x64(N), M-paired acc, dup-B-in-smem -----------
template<int EPI, bool SPLIT>
__global__ __launch_bounds__(256, 3)
void sgemmMN(const float* __restrict__ A, const float* __restrict__ B,
             const float* __restrict__ bias, const float* __restrict__ res,
             float* __restrict__ C, int M, int N, int Kblk, int Ktot){
    __shared__ __align__(16) float As[2][16][132];
    __shared__ __align__(16) ULL  BsD[2][16][64];
    int tid = threadIdx.x;
    int bm = blockIdx.y * 128;
    int bn = blockIdx.x * 64;
    int kOff = SPLIT ? blockIdx.z * Kblk : 0;
    if (SPLIT) C += (size_t)blockIdx.z * M * N;
    int tx = tid & 15, ty = tid >> 4;
    const int KT = Kblk >> 4;

    ULL acc[4][4];
    #pragma unroll
    for (int mp = 0; mp < 4; mp++)
        #pragma unroll
        for (int j = 0; j < 4; j++) acc[mp][j] = 0ULL;

    float4 pa[2], pb;
    auto loadG = [&](int kt){
        #pragma unroll
        for (int i = 0; i < 2; i++){
            int v = tid + i*256;
            int row = v >> 2, kq = (v & 3) * 4;
            pa[i] = *(const float4*)&A[(size_t)(bm + row)*Ktot + kOff + kt*16 + kq];
        }
        int brow = tid >> 4, bc = (tid & 15) * 4;
        pb = *(const float4*)&B[(size_t)(kOff + kt*16 + brow)*N + bn + bc];
    };
    auto storeS = [&](int buf){
        #pragma unroll
        for (int i = 0; i < 2; i++){
            int v = tid + i*256;
            int row = v >> 2, kq = (v & 3) * 4;
            As[buf][kq+0][row] = pa[i].x;
            As[buf][kq+1][row] = pa[i].y;
            As[buf][kq+2][row] = pa[i].z;
            As[buf][kq+3][row] = pa[i].w;
        }
        int brow = tid >> 4, bc = (tid & 15) * 4;
        BsD[buf][brow][bc+0] = dup2(pb.x);
        BsD[buf][brow][bc+1] = dup2(pb.y);
        BsD[buf][brow][bc+2] = dup2(pb.z);
        BsD[buf][brow][bc+3] = dup2(pb.w);
    };

    loadG(0);
    storeS(0);
    __syncthreads();

    for (int kt = 0; kt < KT; kt++){
        int cur = kt & 1;
        if (kt + 1 < KT) loadG(kt + 1);
        #pragma unroll
        for (int k = 0; k < 16; k++){
            ulonglong2 a01 = *(const ulonglong2*)&As[cur][k][ty*8];
            ulonglong2 a23 = *(const ulonglong2*)&As[cur][k][ty*8 + 4];
            ULL am0 = a01.x, am1 = a01.y, am2 = a23.x, am3 = a23.y;
            ULL bd[4];
            #pragma unroll
            for (int j = 0; j < 4; j++) bd[j] = BsD[cur][k][tx + 16*j];
            #pragma unroll
            for (int j = 0; j < 4; j++){
                fma2(acc[0][j], am0, bd[j]);
                fma2(acc[1][j], am1, bd[j]);
                fma2(acc[2][j], am2, bd[j]);
                fma2(acc[3][j], am3, bd[j]);
            }
        }
        if (kt + 1 < KT) storeS(1 - cur);
        __syncthreads();
    }

    #pragma unroll
    for (int mp = 0; mp < 4; mp++){
        int r0 = bm + ty*8 + 2*mp;
        #pragma unroll
        for (int j = 0; j < 4; j++){
            int col = bn + tx + 16*j;
            float2 v = unpack2(acc[mp][j]);
            float o0 = v.x, o1 = v.y;
            if (EPI & 1){ float bx = bias[col]; o0 += bx; o1 += bx; }
            if (EPI & 2){
                o0 += res[(size_t)r0*N + col];
                o1 += res[(size_t)(r0+1)*N + col];
            }
            if (EPI & 4){ o0 = fmaxf(o0, 0.f); o1 = fmaxf(o1, 0.f); }
            C[(size_t)r0*N + col]     = o0;
            C[(size_t)(r0+1)*N + col] = o1;
        }
    }
}

// ------- wide f32x2 SGEMM: 128(M)x128(N), 8x8 microtile, dup-B-in-regs -----------
// Per output element the FFMA2 chain order (kt asc, k asc) matches sgemmMN exactly.
template<int EPI, bool SPLIT>
__global__ __launch_bounds__(256, 2)
void sgemmW(const float* __restrict__ A, const float* __restrict__ B,
            const float* __restrict__ bias, const float* __restrict__ res,
            float* __restrict__ C, int M, int N, int Kblk, int Ktot){
    __shared__ __align__(16) float As[2][16][132];
    __shared__ __align__(16) float Bs[2][16][128];
    int tid = threadIdx.x;
    int bm = blockIdx.y * 128;
    int bn = blockIdx.x * 128;
    int kOff = SPLIT ? blockIdx.z * Kblk : 0;
    if (SPLIT) C += (size_t)blockIdx.z * M * N;
    int tx = tid & 15, ty = tid >> 4;
    const int KT = Kblk >> 4;

    ULL acc[4][8];   // [M-pair][col]  col = 2*(tx+16*(jj>>1)) + (jj&1)
    #pragma unroll
    for (int mp = 0; mp < 4; mp++)
        #pragma unroll
        for (int jj = 0; jj < 8; jj++) acc[mp][jj] = 0ULL;

    float4 pa[2], pb[2];
    auto loadG = [&](int kt){
        #pragma unroll
        for (int i = 0; i < 2; i++){
            int v = tid + i*256;
            int row = v >> 2, kq = (v & 3) * 4;
            pa[i] = *(const float4*)&A[(size_t)(bm + row)*Ktot + kOff + kt*16 + kq];
            int brow = v >> 5, bc = (v & 31) * 4;
            pb[i] = *(const float4*)&B[(size_t)(kOff + kt*16 + brow)*N + bn + bc];
        }
    };
    auto storeS = [&](int buf){
        #pragma unroll
        for (int i = 0; i < 2; i++){
            int v = tid + i*256;
            int row = v >> 2, kq = (v & 3) * 4;
            As[buf][kq+0][row] = pa[i].x;
            As[buf][kq+1][row] = pa[i].y;
            As[buf][kq+2][row] = pa[i].z;
            As[buf][kq+3][row] = pa[i].w;
            int brow = v >> 5, bc = (v & 31) * 4;
            *(float4*)&Bs[buf][brow][bc] = pb[i];
        }
    };

    loadG(0);
    storeS(0);
    __syncthreads();

    for (int kt = 0; kt < KT; kt++){
        int cur = kt & 1;
        if (kt + 1 < KT) loadG(kt + 1);
        #pragma unroll
        for (int k = 0; k < 16; k++){
            ulonglong2 a01 = *(const ulonglong2*)&As[cur][k][ty*8];
            ulonglong2 a23 = *(const ulonglong2*)&As[cur][k][ty*8 + 4];
            ULL am0 = a01.x, am1 = a01.y, am2 = a23.x, am3 = a23.y;
            #pragma unroll
            for (int j = 0; j < 4; j++){
                float2 bf = *(const float2*)&Bs[cur][k][2*(tx + 16*j)];
                ULL b0 = dup2(bf.x), b1 = dup2(bf.y);
                fma2(acc[0][2*j],   am0, b0);
                fma2(acc[1][2*j],   am1, b0);
                fma2(acc[2][2*j],   am2, b0);
                fma2(acc[3][2*j],   am3, b0);
                fma2(acc[0][2*j+1], am0, b1);
                fma2(acc[1][2*j+1], am1, b1);
                fma2(acc[2][2*j+1], am2, b1);
                fma2(acc[3][2*j+1], am3, b1);
            }
        }
        if (kt + 1 < KT) storeS(1 - cur);
        __syncthreads();
    }

    #pragma unroll
    for (int mp = 0; mp < 4; mp++){
        int r0 = bm + ty*8 + 2*mp;
        #pragma unroll
        for (int j = 0; j < 4; j++){
            int col = bn + 2*(tx + 16*j);
            float2 va = unpack2(acc[mp][2*j]);     // col,   rows r0/r0+1
            float2 vb = unpack2(acc[mp][2*j+1]);   // col+1, rows r0/r0+1
            float2 row0 = make_float2(va.x, vb.x);
            float2 row1 = make_float2(va.y, vb.y);
            if (EPI & 1){
                float2 bx = *(const float2*)&bias[col];
                row0.x += bx.x; row0.y += bx.y;
                row1.x += bx.x; row1.y += bx.y;
            }
            if (EPI & 2){
                float2 ra = *(const float2*)&res[(size_t)r0*N + col];
                float2 rb = *(const float2*)&res[(size_t)(r0+1)*N + col];
                row0.x += ra.x; row0.y += ra.y;
                row1.x += rb.x; row1.y += rb.y;
            }
            if (EPI & 4){
                row0.x = fmaxf(row0.x, 0.f); row0.y = fmaxf(row0.y, 0.f);
                row1.x = fmaxf(row1.x, 0.f); row1.y = fmaxf(row1.y, 0.f);
            }
            *(float2*)&C[(size_t)r0*N + col]     = row0;
            *(float2*)&C[(size_t)(r0+1)*N + col] = row1;
        }
    }
}

// ------------- kRLN: split-K(4) reduce + bias0 + LN2, one row per block ----------
__global__ void kRLN(const float* __restrict__ g2, const float* __restrict__ b2){
    __shared__ float red[256];
    int r = blockIdx.x;
    int t = threadIdx.x;
    const size_t MN = (size_t)NC*DD;
    size_t idx = (size_t)r*DD + t;
    float a = g_part[idx];
    a += g_part[MN + idx];
    a += g_part[2*MN + idx];
    a += g_part[3*MN + idx];
    a += g_bias0[t];
    g_x0[idx] = a;
    float mean = blockReduceSum256(a, red) * (1.f/DD);
    float dx = a - mean;
    float var = blockReduceSum256(dx*dx, red) * (1.f/DD);
    g_h2[idx] = dx * rsqrtf(var + 1e-5f) * g2[t] + b2[t];
}

// ---------------- split-K reduce + epilogue (elementwise) ----------------
template<int EPI>
__global__ void kReduce(const float* __restrict__ part, const float* __restrict__ bias,
                        const float* __restrict__ res, float* __restrict__ C,
                        int MN4, int N, int S){
    int v = blockIdx.x * 256 + threadIdx.x;
    if (v >= MN4) return;
    const float4* P = (const float4*)part;
    float4 a = P[v];
    for (int z = 1; z < S; z++){
        float4 p = P[(size_t)z*MN4 + v];
        a.x += p.x; a.y += p.y; a.z += p.z; a.w += p.w;
    }
    if (EPI & 1){
        int col = (v*4) & (N-1);
        float4 bb = *(const float4*)&bias[col];
        a.x += bb.x; a.y += bb.y; a.z += bb.z; a.w += bb.w;
    }
    if (EPI & 2){
        float4 r = ((const float4*)res)[v];
        a.x += r.x; a.y += r.y; a.z += r.z; a.w += r.w;
    }
    if (EPI & 4){
        a.x = fmaxf(a.x, 0.f); a.y = fmaxf(a.y, 0.f);
        a.z = fmaxf(a.z, 0.f); a.w = fmaxf(a.w, 0.f);
    }
    ((float4*)C)[v] = a;
}

// -------- kRZ: split-K(4) reduce + be1 + relu + logit + lstar per (b,i) ----------
__global__ void kRZ(const float* __restrict__ be1, const float* __restrict__ We2,
                    const float* __restrict__ be2){
    __shared__ float logit[LL];
    int blk = blockIdx.x;
    int t = threadIdx.x;
    int w = t >> 5, lane = t & 31;
    const size_t MN = (size_t)NC*DD;
    size_t rowOff = (size_t)(blk*LL + w)*DD;
    float s = 0.f;
    #pragma unroll
    for (int j = 0; j < 8; j++){
        int d = lane + 32*j;
        size_t idx = rowOff + d;
        float a = g_part[idx];
        a += g_part[MN + idx];
        a += g_part[2*MN + idx];
        a += g_part[3*MN + idx];
        a += be1[d];
        s += fmaxf(a, 0.f) * We2[d];
    }
    #pragma unroll
    for (int o = 16; o; o >>= 1) s += __shfl_down_sync(0xffffffffu, s, o);
    if (lane == 0) logit[w] = s + be2[0];
    __syncthreads();
    if (t == 0){
        int i = blk & 127;
        int lmax = TT - i; if (lmax > LL) lmax = LL;
        int lstar = lmax;
        for (int l = 1; l <= lmax; l++){
            if (logit[l-1] > 0.f){ lstar = l; break; }
        }
        g_lstar[blk] = lstar;
    }
}

// ---------------- chain resolution + output ----------------
__global__ void kChain(){
    int b = threadIdx.x;
    if (b < BB){
        int i = 0, cnt = 0;
        for (int s = 0; s < TT; s++){
            if (i < TT){
                int ls = g_lstar[b*TT + i];
                g_slot[b*TT + s] = (b*TT + i)*LL + (ls - 1);
                i += ls;
                cnt++;
            } else g_slot[b*TT + s] = -1;
        }
        g_cnt[b] = cnt;
    }
}

__global__ void kOut(float* __restrict__ out, int out_size){
    int r = blockIdx.x;
    int t = threadIdx.x;
    int c = g_slot[r];
    out[(size_t)r*DD + t] = (c >= 0) ? g_enc[(size_t)c*DD + t] : 0.f;
    if (r == 0 && t < BB && out_size > BB*TT*DD + t)
        out[BB*TT*DD + t] = (float)g_cnt[t];
}

// ---------------- launch ----------------
extern "C" void kernel_launch(void* const* d_in, const int* in_sizes, int n_in,
                              void* d_out, int out_size){
    const float* frames = (const float*)d_in[0];
    const float* cls    = (const float*)d_in[1];
    const float* Wq  = (const float*)d_in[2];  const float* bq  = (const float*)d_in[3];
    const float* Wk  = (const float*)d_in[4];  const float* bk  = (const float*)d_in[5];
    const float* Wv  = (const float*)d_in[6];  const float* bv  = (const float*)d_in[7];
    const float* Wo  = (const float*)d_in[8];  const float* bo  = (const float*)d_in[9];
    const float* ln1g= (const float*)d_in[10]; const float* ln1b= (const float*)d_in[11];
    const float* ln2g= (const float*)d_in[12]; const float* ln2b= (const float*)d_in[13];
    const float* W1  = (const float*)d_in[14]; const float* b1f = (const float*)d_in[15];
    const float* W2  = (const float*)d_in[16]; const float* b2f = (const float*)d_in[17];
    const float* We1 = (const float*)d_in[18]; const float* be1 = (const float*)d_in[19];
    const float* We2 = (const float*)d_in[20]; const float* be2 = (const float*)d_in[21];
    float* out = (float*)d_out;

    float *p_o0, *p_x0, *p_h2, *p_u, *p_enc, *p_part;
    cudaGetSymbolAddress((void**)&p_o0,   g_o0);
    cudaGetSymbolAddress((void**)&p_x0,   g_x0);
    cudaGetSymbolAddress((void**)&p_h2,   g_h2);
    cudaGetSymbolAddress((void**)&p_u,    g_u);
    cudaGetSymbolAddress((void**)&p_enc,  g_enc);
    cudaGetSymbolAddress((void**)&p_part, g_part);

    const int MN4 = NC*DD/4;
    const int RB  = MN4/256;

    kC<<<1, 256>>>(cls, Wq, bq, Wk, bk, Wv, bv, bo, ln1g, ln1b);
    kP<<<BT/4, 256>>>(frames, Wk, bk, Wv, bv, ln1g, ln1b);
    kA<<<BT, 256>>>();

    // GEMM1 partials: o0 @ Wo   [split-K=4, Kblk=64] (narrow)
    sgemmMN<0, true><<<dim3(DD/64, NC/128, 4), 256>>>(p_o0, Wo, nullptr, nullptr, p_part, NC, DD, 64, DD);
    // x0 = partials + (cls+bo); h2 = LN2(x0)   [fused]
    kRLN<<<NC, 256>>>(ln2g, ln2b);
    // u = relu(h2 @ W1 + b1f)   (wide)
    sgemmW<5, false><<<dim3(FF/128, NC/128, 1), 256>>>(p_h2, W1, b1f, nullptr, p_u, NC, FF, DD, DD);
    // enc = u @ W2 + b2f + x0   [split-K=8, Kblk=256] (wide)
    sgemmW<0, true><<<dim3(DD/128, NC/128, 8), 256>>>(p_u, W2, nullptr, nullptr, p_part, NC, DD, 256, FF);
    kReduce<3><<<RB, 256>>>(p_part, b2f, p_x0, p_enc, MN4, DD, 8);
    // GEMM4 partials: enc @ We1   [split-K=4, Kblk=64] (narrow)
    sgemmMN<0, true><<<dim3(DD/64, NC/128, 4), 256>>>(p_enc, We1, nullptr, nullptr, p_part, NC, DD, 64, DD);
    // fused reduce + relu + logit + lstar
    kRZ<<<BT, 256>>>(be1, We2, be2);

    kChain<<<1, 32>>>();
    kOut<<<BT, 256>>>(out, out_size);
}